// round 6
// baseline (speedup 1.0000x reference)
#include <cuda_runtime.h>
#include <cuda_bf16.h>
#include <cstdint>

#define T_ 2
#define C_ 64
#define H_ 160
#define W_ 160
#define KS 7
#define K2 49
#define NSPIX 196
#define FAN 3136

#define TH 16
#define TW 16
#define NPIX 256       // TH*TW
#define XR 22          // TH+6
#define XC 22          // TW+6
#define NS 484         // XR*XC
#define HROW 272       // 128 hi + 128 lo + 16 pad (stride = 4 banks mod 32)

// ---- dynamic smem layout (bytes) ----
#define OFF_HALO   0                   // 484*272 = 131648
#define OFF_B      131648              // 2 bufs * 16384 = 32768
#define OFF_RW     164416              // 256*49*4 = 50176
#define OFF_SCALE  214592              // 256*4 = 1024
#define SMEM_MAIN  215616

#define PWD_SMEM   (64*196*4 + 196*4)  // 50960

// ---- global scratch ----
__device__ float g_sums[T_*NSPIX*C_];
__device__ float g_cnts[T_*NSPIX];
__device__ float g_pwd[T_*NSPIX*NSPIX];
// per k: [hi 8192B][lo 8192B], each 64o x 64c bf16, XOR-16B swizzled rows
__device__ __align__(16) __nv_bfloat16 g_Wsp[K2*2*C_*C_];

__device__ __forceinline__ int refl(int i, int n){
    if (i < 0) i = -i;
    if (i >= n) i = 2*n - 2 - i;
    return i;
}

__device__ __forceinline__ uint32_t smem_u32(const void* p){
    uint32_t a;
    asm("{ .reg .u64 t; cvta.to.shared.u64 t, %1; cvt.u32.u64 %0, t; }" : "=r"(a) : "l"(p));
    return a;
}

__device__ __forceinline__ void ldsm4(uint32_t* r, uint32_t addr){
    asm volatile("ldmatrix.sync.aligned.m8n8.x4.shared.b16 {%0,%1,%2,%3}, [%4];"
        : "=r"(r[0]), "=r"(r[1]), "=r"(r[2]), "=r"(r[3]) : "r"(addr));
}

__device__ __forceinline__ void mma16816(float* d, const uint32_t* a, const uint32_t* b){
    asm volatile("mma.sync.aligned.m16n8k16.row.col.f32.bf16.bf16.f32 "
        "{%0,%1,%2,%3}, {%4,%5,%6,%7}, {%8,%9}, {%0,%1,%2,%3};"
        : "+f"(d[0]), "+f"(d[1]), "+f"(d[2]), "+f"(d[3])
        : "r"(a[0]), "r"(a[1]), "r"(a[2]), "r"(a[3]), "r"(b[0]), "r"(b[1]));
}

__device__ __forceinline__ void cpa16(uint32_t dst, const void* src){
    asm volatile("cp.async.cg.shared.global [%0], [%1], 16;" :: "r"(dst), "l"(src) : "memory");
}
#define CP_COMMIT() asm volatile("cp.async.commit_group;" ::: "memory")
#define CP_WAIT(n)  asm volatile("cp.async.wait_group %0;" :: "n"(n) : "memory")

// ========================= prep kernels =========================

__global__ void zero_kernel(){
    int i = blockIdx.x*blockDim.x + threadIdx.x;
    if (i < T_*NSPIX*C_) g_sums[i] = 0.f;
    if (i < T_*NSPIX)    g_cnts[i] = 0.f;
}

// grid 64 (one block per o). Coalesced read of W row via smem staging.
__global__ void wsplit_kernel(const float* __restrict__ W){
    __shared__ float wrow[FAN];
    int o = blockIdx.x;
    int tid = threadIdx.x;
    for (int i = tid; i < FAN; i += 256) wrow[i] = W[o*FAN + i];
    __syncthreads();
    uint32_t oxor = (uint32_t)((o & 7) << 4);
    for (int idx = tid; idx < FAN; idx += 256){
        int k = idx >> 6, c = idx & 63;
        float v = wrow[c*K2 + k];
        uint32_t u = __float_as_uint(v);
        float hif = __uint_as_float(u & 0xFFFF0000u);
        float lof = v - hif;
        uint32_t boff = (uint32_t)(o*128) + ((((uint32_t)(c>>3))<<4) ^ oxor) + (uint32_t)((c&7)*2);
        char* base = (char*)g_Wsp + (size_t)k*16384;
        *(unsigned short*)(base + boff) = (unsigned short)(u >> 16);
        __nv_bfloat16 lb = __float2bfloat16_rn(lof);
        *(__nv_bfloat16*)(base + 8192 + boff) = lb;
    }
}

// one warp per pixel: lanes = channels -> coalesced RED
__global__ void accum_kernel(const float* __restrict__ x, const int* __restrict__ spix){
    int tid = threadIdx.x;
    int wi = tid >> 5, l = tid & 31;
    int pix = blockIdx.x*8 + wi;
    if (pix >= T_*H_*W_) return;
    int t = pix / (H_*W_);
    int hw = pix - t*(H_*W_);
    int s = spix[pix];
    const float* xp = x + (size_t)t*C_*H_*W_ + hw;
    float v0 = xp[(size_t)l*(H_*W_)];
    float v1 = xp[(size_t)(l+32)*(H_*W_)];
    float* dst = &g_sums[(t*NSPIX + s)*C_];
    atomicAdd(&dst[l],      v0);
    atomicAdd(&dst[l + 32], v1);
    if (l == 0) atomicAdd(&g_cnts[t*NSPIX + s], 1.0f);
}

// grid T_*49, 256 threads, dyn smem: down_t[64][196] + sq[196]
__global__ void pwd_kernel(){
    extern __shared__ float sm[];
    float* down_t = sm;
    float* sq = sm + 64*196;
    int t  = blockIdx.x / 49;
    int ub = (blockIdx.x % 49) * 4;
    int tid = threadIdx.x;
    for (int i = tid; i < 64*196; i += 256){
        int c = i / 196, s = i - c*196;
        down_t[i] = g_sums[(t*NSPIX + s)*C_ + c] / fmaxf(g_cnts[t*NSPIX + s], 1.f);
    }
    __syncthreads();
    for (int s = tid; s < 196; s += 256){
        float q = 0.f;
        #pragma unroll 8
        for (int c = 0; c < 64; c++){ float v = down_t[c*196 + s]; q += v*v; }
        sq[s] = q;
    }
    __syncthreads();
    if (tid < 196){
        int s0 = (tid % 98)*2;
        int u0 = ub + (tid / 98)*2;
        float d00=0.f, d01=0.f, d10=0.f, d11=0.f;
        #pragma unroll 8
        for (int c = 0; c < 64; c++){
            float a0 = down_t[c*196 + s0], a1 = down_t[c*196 + s0 + 1];
            float b0 = down_t[c*196 + u0], b1 = down_t[c*196 + u0 + 1];
            d00 += a0*b0; d01 += a0*b1; d10 += a1*b0; d11 += a1*b1;
        }
        float* dst = &g_pwd[(size_t)(t*NSPIX + s0)*NSPIX];
        dst[u0]         = fmaxf(sq[s0]   + sq[u0]   - 2.f*d00, 0.f);
        dst[u0+1]       = fmaxf(sq[s0]   + sq[u0+1] - 2.f*d01, 0.f);
        dst[NSPIX+u0]   = fmaxf(sq[s0+1] + sq[u0]   - 2.f*d10, 0.f);
        dst[NSPIX+u0+1] = fmaxf(sq[s0+1] + sq[u0+1] - 2.f*d11, 0.f);
    }
}

// ========================= main kernel =========================
// 200 CTAs (16x16 px tiles), 256 threads (8 warps: 4m x 2n), occ 1.

__global__ void __launch_bounds__(256, 1) main_kernel(
    const float* __restrict__ x, const int* __restrict__ spix,
    const float* __restrict__ b_lin, const float* __restrict__ w_scale,
    const float* __restrict__ b_scale, float* __restrict__ out)
{
    extern __shared__ char smem[];
    uint32_t sb = smem_u32(smem);
    int tid = threadIdx.x;
    int wi = tid >> 5, l = tid & 31;
    int mi = wi >> 1, ni = wi & 1;
    int t = blockIdx.z;
    int gh0 = blockIdx.y*TH, gw0 = blockIdx.x*TW;

    float* scale_s = (float*)(smem + OFF_SCALE);
    float* rw      = (float*)(smem + OFF_RW);

    // ---- phase 1: per-pixel scale ----
    {
        int gh = gh0 + (tid >> 4), gw = gw0 + (tid & 15);
        const float* xp = x + (size_t)t*C_*H_*W_ + gh*W_ + gw;
        float nsq = 0.f, dot = 0.f;
        #pragma unroll 8
        for (int c = 0; c < C_; c++){
            float v = xp[(size_t)c*H_*W_];
            nsq += v*v;
            dot += w_scale[c]*v;
        }
        float z  = dot / (sqrtf(nsq) + 1e-10f) + b_scale[0];
        float sp = fmaxf(z, 0.f) + log1pf(expf(-fabsf(z)));
        scale_s[tid] = 10.f * sp;
    }

    // ---- phase 2: halo load + hi/lo split: row s = [hi 128B][lo 128B][pad16] ----
    for (int i = tid; i < NS*32; i += 256){
        int s  = i >> 5;
        int cp = i & 31;
        int rr = s / XC, cc2 = s - rr*XC;
        int gh = refl(gh0 + rr - 3, H_), gw = refl(gw0 + cc2 - 3, W_);
        const float* xp = x + ((size_t)(t*C_ + 2*cp)*H_ + gh)*W_ + gw;
        float v0 = xp[0], v1 = xp[(size_t)H_*W_];
        uint32_t u0 = __float_as_uint(v0), u1 = __float_as_uint(v1);
        uint32_t hp = __byte_perm(u0, u1, 0x7632);
        float l0 = v0 - __uint_as_float(u0 & 0xFFFF0000u);
        float l1 = v1 - __uint_as_float(u1 & 0xFFFF0000u);
        __nv_bfloat162 lp2 = __floats2bfloat162_rn(l0, l1);
        *(uint32_t*)(smem + OFF_HALO + s*HROW + cp*4)       = hp;
        *(uint32_t*)(smem + OFF_HALO + s*HROW + 128 + cp*4) = *(uint32_t*)&lp2;
    }
    __syncthreads();

    // ---- phase 3: rw ----
    for (int item = tid; item < NPIX*K2; item += 256){
        int p  = item / K2, k = item - p*K2;
        int ki = k / KS,  kj = k - ki*KS;
        int gh = gh0 + (p >> 4), gw = gw0 + (p & 15);
        int rh = refl(gh + ki - 3, H_), rc = refl(gw + kj - 3, W_);
        int sc = spix[(t*H_ + gh)*W_ + gw];
        int nb = spix[(t*H_ + rh)*W_ + rc];
        rw[item] = expf(-scale_s[p] * g_pwd[(size_t)(t*NSPIX + sc)*NSPIX + nb]);
    }
    __syncthreads();
    {
        float m = 0.f;
        #pragma unroll
        for (int k = 0; k < K2; k++) m = fmaxf(m, rw[tid*K2 + k]);
        float inv = 1.f / (1e-5f + m);
        #pragma unroll
        for (int k = 0; k < K2; k++) rw[tid*K2 + k] *= inv;
    }

    // ---- per-lane static addressing ----
    int rowA = (l & 7) | (((l >> 3) & 1) << 3);
    int colh = (l >> 4) & 1;
    uint32_t aBase[4];
    #pragma unroll
    for (int mt = 0; mt < 4; mt++)
        aBase[mt] = sb + OFF_HALO + (uint32_t)(((mi*4 + mt)*XC + rowA)*HROW) + colh*16;

    int oRow  = (l & 7) | (((l >> 4) & 1) << 3);
    uint32_t bhalf16 = (uint32_t)(((l >> 3) & 1) << 4);
    uint32_t oxor = (uint32_t)((l & 7) << 4);
    uint32_t bRow[2];
    #pragma unroll
    for (int nh = 0; nh < 2; nh++)
        bRow[nh] = (uint32_t)((ni*32 + nh*16 + oRow)*128);

    // ---- preload B for k=0 ----
    {
        const char* src = (const char*)g_Wsp;
        uint32_t dst = sb + OFF_B;
        #pragma unroll
        for (int j = 0; j < 4; j++){
            int idx = tid + j*256;
            cpa16(dst + idx*16, src + idx*16);
        }
        CP_COMMIT();
    }

    float acc[64];
    #pragma unroll
    for (int i = 0; i < 64; i++) acc[i] = 0.f;

    // ---- main loop over 49 kernel offsets ----
    for (int k = 0; k < K2; k++){
        int cur = k & 1;
        if (k + 1 < K2){
            const char* src = (const char*)g_Wsp + (size_t)(k+1)*16384;
            uint32_t dst = sb + OFF_B + (cur^1)*16384;
            #pragma unroll
            for (int j = 0; j < 4; j++){
                int idx = tid + j*256;
                cpa16(dst + idx*16, src + idx*16);
            }
            CP_COMMIT();
            CP_WAIT(1);
        } else {
            CP_WAIT(0);
        }
        __syncthreads();

        // hoist B fragments for this k into registers (hi + lo)
        uint32_t bBase = sb + OFF_B + cur*16384;
        uint32_t bh[32], bl[32];
        #pragma unroll
        for (int kc = 0; kc < 4; kc++){
            #pragma unroll
            for (int nh = 0; nh < 2; nh++){
                uint32_t addr = bBase + bRow[nh] + (((uint32_t)(kc*32) + bhalf16) ^ oxor);
                ldsm4(&bh[kc*8 + nh*4], addr);
                ldsm4(&bl[kc*8 + nh*4], addr + 8192);
            }
        }
        __syncthreads();   // all warps done reading B smem before next prefetch overwrites

        int ki = k / KS, kj = k - ki*KS;
        uint32_t koff = (uint32_t)((ki*XC + kj)*HROW);

        #pragma unroll
        for (int mt = 0; mt < 4; mt++){
            float d[16];
            #pragma unroll
            for (int i = 0; i < 16; i++) d[i] = 0.f;

            #pragma unroll
            for (int kc = 0; kc < 4; kc++){
                uint32_t aH[4], aL[4];
                uint32_t aAddr = aBase[mt] + koff + kc*32;
                ldsm4(aH, aAddr);
                ldsm4(aL, aAddr + 128);
                // pass hi*hi
                #pragma unroll
                for (int nh = 0; nh < 2; nh++){
                    mma16816(&d[nh*8 + 0], aH, &bh[kc*8 + nh*4]);
                    mma16816(&d[nh*8 + 4], aH, &bh[kc*8 + nh*4 + 2]);
                }
                // pass lo*hi
                #pragma unroll
                for (int nh = 0; nh < 2; nh++){
                    mma16816(&d[nh*8 + 0], aL, &bh[kc*8 + nh*4]);
                    mma16816(&d[nh*8 + 4], aL, &bh[kc*8 + nh*4 + 2]);
                }
                // pass hi*lo
                #pragma unroll
                for (int nh = 0; nh < 2; nh++){
                    mma16816(&d[nh*8 + 0], aH, &bl[kc*8 + nh*4]);
                    mma16816(&d[nh*8 + 4], aH, &bl[kc*8 + nh*4 + 2]);
                }
            }

            // weight by rw and accumulate
            int p_lo = mi*64 + mt*16 + (l >> 2);
            float r_lo = rw[p_lo*K2 + k];
            float r_hi = rw[(p_lo + 8)*K2 + k];
            #pragma unroll
            for (int j = 0; j < 16; j += 4){
                acc[mt*16 + j + 0] += r_lo*d[j + 0];
                acc[mt*16 + j + 1] += r_lo*d[j + 1];
                acc[mt*16 + j + 2] += r_hi*d[j + 2];
                acc[mt*16 + j + 3] += r_hi*d[j + 3];
            }
        }
    }

    // ---- store ----
    #pragma unroll
    for (int mt = 0; mt < 4; mt++){
        int gh  = gh0 + mi*4 + mt;
        int gwl = gw0 + (l >> 2);
        int gwh = gwl + 8;
        #pragma unroll
        for (int nh = 0; nh < 2; nh++){
            #pragma unroll
            for (int q = 0; q < 2; q++){
                int o = ni*32 + nh*16 + q*8 + 2*(l & 3);
                float b0 = b_lin[o], b1 = b_lin[o+1];
                float* r0 = out + ((size_t)(t*C_ + o  )*H_ + gh)*W_;
                float* r1 = out + ((size_t)(t*C_ + o+1)*H_ + gh)*W_;
                int j = mt*16 + nh*8 + q*4;
                r0[gwl] = acc[j + 0] + b0;
                r1[gwl] = acc[j + 1] + b1;
                r0[gwh] = acc[j + 2] + b0;
                r1[gwh] = acc[j + 3] + b1;
            }
        }
    }
}

// ========================= launch =========================

extern "C" void kernel_launch(void* const* d_in, const int* in_sizes, int n_in,
                              void* d_out, int out_size)
{
    const float* x       = (const float*)d_in[0];
    const int*   spix    = (const int*)  d_in[1];
    const float* W       = (const float*)d_in[2];
    const float* b_lin   = (const float*)d_in[3];
    const float* w_scale = (const float*)d_in[4];
    const float* b_scale = (const float*)d_in[5];
    float* out = (float*)d_out;

    cudaFuncSetAttribute(pwd_kernel,  cudaFuncAttributeMaxDynamicSharedMemorySize, PWD_SMEM);
    cudaFuncSetAttribute(main_kernel, cudaFuncAttributeMaxDynamicSharedMemorySize, SMEM_MAIN);

    zero_kernel  <<<(T_*NSPIX*C_ + 255)/256, 256>>>();
    wsplit_kernel<<<C_, 256>>>(W);
    accum_kernel <<<(T_*H_*W_ + 7)/8, 256>>>(x, spix);
    pwd_kernel   <<<T_*49, 256, PWD_SMEM>>>();

    dim3 grid(W_/TW, H_/TH, T_);
    main_kernel<<<grid, 256, SMEM_MAIN>>>(x, spix, b_lin, w_scale, b_scale, out);
}

// round 7
// speedup vs baseline: 1.1691x; 1.1691x over previous
#include <cuda_runtime.h>
#include <cuda_bf16.h>
#include <cstdint>

#define T_ 2
#define C_ 64
#define H_ 160
#define W_ 160
#define KS 7
#define K2 49
#define NSPIX 196
#define FAN 3136

#define TH 8
#define TW 8
#define NPIX 64        // TH*TW
#define XR 14          // TH+6
#define XC 14          // TW+6
#define NS 196         // XR*XC
#define HROW 272       // 128 hi + 128 lo + 16 pad (stride = 4 banks mod 32)

// ---- dynamic smem layout (bytes) ----
#define OFF_HALO   0                   // 196*272 = 53312
#define OFF_B      53312               // 2 bufs * 16384 = 32768
#define OFF_RW     86080               // 64*49*4 = 12544
#define OFF_SCALE  98624               // 64*4 = 256
#define SMEM_MAIN  98880

#define PWD_SMEM   (64*196*4 + 196*4)  // 50960

// ---- global scratch ----
__device__ float g_sums[T_*NSPIX*C_];
__device__ float g_cnts[T_*NSPIX];
__device__ float g_pwd[T_*NSPIX*NSPIX];
// per k: [hi 8192B][lo 8192B], each 64o x 64c bf16, XOR-16B swizzled rows
__device__ __align__(16) __nv_bfloat16 g_Wsp[K2*2*C_*C_];

__device__ __forceinline__ int refl(int i, int n){
    if (i < 0) i = -i;
    if (i >= n) i = 2*n - 2 - i;
    return i;
}

__device__ __forceinline__ uint32_t smem_u32(const void* p){
    uint32_t a;
    asm("{ .reg .u64 t; cvta.to.shared.u64 t, %1; cvt.u32.u64 %0, t; }" : "=r"(a) : "l"(p));
    return a;
}

__device__ __forceinline__ void ldsm4(uint32_t* r, uint32_t addr){
    asm volatile("ldmatrix.sync.aligned.m8n8.x4.shared.b16 {%0,%1,%2,%3}, [%4];"
        : "=r"(r[0]), "=r"(r[1]), "=r"(r[2]), "=r"(r[3]) : "r"(addr));
}

__device__ __forceinline__ void mma16816(float* d, const uint32_t* a, const uint32_t* b){
    asm volatile("mma.sync.aligned.m16n8k16.row.col.f32.bf16.bf16.f32 "
        "{%0,%1,%2,%3}, {%4,%5,%6,%7}, {%8,%9}, {%0,%1,%2,%3};"
        : "+f"(d[0]), "+f"(d[1]), "+f"(d[2]), "+f"(d[3])
        : "r"(a[0]), "r"(a[1]), "r"(a[2]), "r"(a[3]), "r"(b[0]), "r"(b[1]));
}

__device__ __forceinline__ void cpa16(uint32_t dst, const void* src){
    asm volatile("cp.async.cg.shared.global [%0], [%1], 16;" :: "r"(dst), "l"(src) : "memory");
}
#define CP_COMMIT() asm volatile("cp.async.commit_group;" ::: "memory")
#define CP_WAIT(n)  asm volatile("cp.async.wait_group %0;" :: "n"(n) : "memory")

// ========================= prep kernels =========================

__global__ void zero_kernel(){
    int i = blockIdx.x*blockDim.x + threadIdx.x;
    if (i < T_*NSPIX*C_) g_sums[i] = 0.f;
    if (i < T_*NSPIX)    g_cnts[i] = 0.f;
}

// grid 64 (one block per o). Coalesced read of W row via smem staging.
__global__ void wsplit_kernel(const float* __restrict__ W){
    __shared__ float wrow[FAN];
    int o = blockIdx.x;
    int tid = threadIdx.x;
    for (int i = tid; i < FAN; i += 256) wrow[i] = W[o*FAN + i];
    __syncthreads();
    uint32_t oxor = (uint32_t)((o & 7) << 4);
    for (int idx = tid; idx < FAN; idx += 256){
        int k = idx >> 6, c = idx & 63;
        float v = wrow[c*K2 + k];
        uint32_t u = __float_as_uint(v);
        float hif = __uint_as_float(u & 0xFFFF0000u);
        float lof = v - hif;
        uint32_t boff = (uint32_t)(o*128) + ((((uint32_t)(c>>3))<<4) ^ oxor) + (uint32_t)((c&7)*2);
        char* base = (char*)g_Wsp + (size_t)k*16384;
        *(unsigned short*)(base + boff) = (unsigned short)(u >> 16);
        __nv_bfloat16 lb = __float2bfloat16_rn(lof);
        *(__nv_bfloat16*)(base + 8192 + boff) = lb;
    }
}

// one warp per pixel: lanes = channels -> coalesced RED
__global__ void accum_kernel(const float* __restrict__ x, const int* __restrict__ spix){
    int tid = threadIdx.x;
    int wi = tid >> 5, l = tid & 31;
    int pix = blockIdx.x*8 + wi;
    if (pix >= T_*H_*W_) return;
    int t = pix / (H_*W_);
    int hw = pix - t*(H_*W_);
    int s = spix[pix];
    const float* xp = x + (size_t)t*C_*H_*W_ + hw;
    float v0 = xp[(size_t)l*(H_*W_)];
    float v1 = xp[(size_t)(l+32)*(H_*W_)];
    float* dst = &g_sums[(t*NSPIX + s)*C_];
    atomicAdd(&dst[l],      v0);
    atomicAdd(&dst[l + 32], v1);
    if (l == 0) atomicAdd(&g_cnts[t*NSPIX + s], 1.0f);
}

// grid T_*49, 256 threads, dyn smem: down_t[64][196] + sq[196]
__global__ void pwd_kernel(){
    extern __shared__ float sm[];
    float* down_t = sm;
    float* sq = sm + 64*196;
    int t  = blockIdx.x / 49;
    int ub = (blockIdx.x % 49) * 4;
    int tid = threadIdx.x;
    for (int i = tid; i < 64*196; i += 256){
        int c = i / 196, s = i - c*196;
        down_t[i] = g_sums[(t*NSPIX + s)*C_ + c] / fmaxf(g_cnts[t*NSPIX + s], 1.f);
    }
    __syncthreads();
    for (int s = tid; s < 196; s += 256){
        float q = 0.f;
        #pragma unroll 8
        for (int c = 0; c < 64; c++){ float v = down_t[c*196 + s]; q += v*v; }
        sq[s] = q;
    }
    __syncthreads();
    if (tid < 196){
        int s0 = (tid % 98)*2;
        int u0 = ub + (tid / 98)*2;
        float d00=0.f, d01=0.f, d10=0.f, d11=0.f;
        #pragma unroll 8
        for (int c = 0; c < 64; c++){
            float a0 = down_t[c*196 + s0], a1 = down_t[c*196 + s0 + 1];
            float b0 = down_t[c*196 + u0], b1 = down_t[c*196 + u0 + 1];
            d00 += a0*b0; d01 += a0*b1; d10 += a1*b0; d11 += a1*b1;
        }
        float* dst = &g_pwd[(size_t)(t*NSPIX + s0)*NSPIX];
        dst[u0]         = fmaxf(sq[s0]   + sq[u0]   - 2.f*d00, 0.f);
        dst[u0+1]       = fmaxf(sq[s0]   + sq[u0+1] - 2.f*d01, 0.f);
        dst[NSPIX+u0]   = fmaxf(sq[s0+1] + sq[u0]   - 2.f*d10, 0.f);
        dst[NSPIX+u0+1] = fmaxf(sq[s0+1] + sq[u0+1] - 2.f*d11, 0.f);
    }
}

// ========================= main kernel =========================
// 800 CTAs (8x8 px tiles), 256 threads (8 warps: 4m x 2n), occ 2 -> 16 warps/SM.

__global__ void __launch_bounds__(256, 2) main_kernel(
    const float* __restrict__ x, const int* __restrict__ spix,
    const float* __restrict__ b_lin, const float* __restrict__ w_scale,
    const float* __restrict__ b_scale, float* __restrict__ out)
{
    extern __shared__ char smem[];
    uint32_t sb = smem_u32(smem);
    int tid = threadIdx.x;
    int wi = tid >> 5, l = tid & 31;
    int mi = wi >> 1, ni = wi & 1;
    int t = blockIdx.z;
    int gh0 = blockIdx.y*TH, gw0 = blockIdx.x*TW;

    float* scale_s = (float*)(smem + OFF_SCALE);
    float* rw      = (float*)(smem + OFF_RW);

    // ---- phase 1: per-pixel scale ----
    if (tid < NPIX){
        int gh = gh0 + (tid >> 3), gw = gw0 + (tid & 7);
        const float* xp = x + (size_t)t*C_*H_*W_ + gh*W_ + gw;
        float nsq = 0.f, dot = 0.f;
        #pragma unroll 8
        for (int c = 0; c < C_; c++){
            float v = xp[(size_t)c*H_*W_];
            nsq += v*v;
            dot += w_scale[c]*v;
        }
        float z  = dot / (sqrtf(nsq) + 1e-10f) + b_scale[0];
        float sp = fmaxf(z, 0.f) + log1pf(expf(-fabsf(z)));
        scale_s[tid] = 10.f * sp;
    }

    // ---- phase 2: halo load + hi/lo split: row s = [hi 128B][lo 128B][pad16] ----
    for (int i = tid; i < NS*32; i += 256){
        int s  = i >> 5;
        int cp = i & 31;
        int rr = s / XC, cc2 = s - rr*XC;
        int gh = refl(gh0 + rr - 3, H_), gw = refl(gw0 + cc2 - 3, W_);
        const float* xp = x + ((size_t)(t*C_ + 2*cp)*H_ + gh)*W_ + gw;
        float v0 = xp[0], v1 = xp[(size_t)H_*W_];
        uint32_t u0 = __float_as_uint(v0), u1 = __float_as_uint(v1);
        uint32_t hp = __byte_perm(u0, u1, 0x7632);
        float l0 = v0 - __uint_as_float(u0 & 0xFFFF0000u);
        float l1 = v1 - __uint_as_float(u1 & 0xFFFF0000u);
        __nv_bfloat162 lp2 = __floats2bfloat162_rn(l0, l1);
        *(uint32_t*)(smem + OFF_HALO + s*HROW + cp*4)       = hp;
        *(uint32_t*)(smem + OFF_HALO + s*HROW + 128 + cp*4) = *(uint32_t*)&lp2;
    }
    __syncthreads();

    // ---- phase 3: rw ----
    for (int item = tid; item < NPIX*K2; item += 256){
        int p  = item / K2, k = item - p*K2;
        int ki = k / KS,  kj = k - ki*KS;
        int gh = gh0 + (p >> 3), gw = gw0 + (p & 7);
        int rh = refl(gh + ki - 3, H_), rc = refl(gw + kj - 3, W_);
        int sc = spix[(t*H_ + gh)*W_ + gw];
        int nb = spix[(t*H_ + rh)*W_ + rc];
        rw[item] = expf(-scale_s[p] * g_pwd[(size_t)(t*NSPIX + sc)*NSPIX + nb]);
    }
    __syncthreads();
    if (tid < NPIX){
        float m = 0.f;
        #pragma unroll
        for (int k = 0; k < K2; k++) m = fmaxf(m, rw[tid*K2 + k]);
        float inv = 1.f / (1e-5f + m);
        #pragma unroll
        for (int k = 0; k < K2; k++) rw[tid*K2 + k] *= inv;
    }

    // ---- per-lane static addressing ----
    int rowA = (l & 7) | (((l >> 3) & 1) << 3);
    int colh = (l >> 4) & 1;
    int pA   = mi*16 + rowA;
    uint32_t aStat = sb + OFF_HALO + (uint32_t)(((pA >> 3)*XC + (pA & 7))*HROW) + colh*16;

    int oRow  = (l & 7) | (((l >> 4) & 1) << 3);
    uint32_t bhalf16 = (uint32_t)(((l >> 3) & 1) << 4);
    int o0 = (ni*2)*16 + oRow;
    int o1 = (ni*2+1)*16 + oRow;
    uint32_t bOff0 = (uint32_t)(o0*128), bXor0 = (uint32_t)((o0 & 7) << 4);
    uint32_t bOff1 = (uint32_t)(o1*128), bXor1 = (uint32_t)((o1 & 7) << 4);

    // ---- preload B for k=0 (16KB, 1024 x 16B, 4 per thread) ----
    {
        const char* src = (const char*)g_Wsp;
        uint32_t dst = sb + OFF_B;
        #pragma unroll
        for (int j = 0; j < 4; j++){
            int idx = tid + j*256;
            cpa16(dst + idx*16, src + idx*16);
        }
        CP_COMMIT();
    }

    float acc[16];
    #pragma unroll
    for (int i = 0; i < 16; i++) acc[i] = 0.f;

    int p_lo = mi*16 + (l >> 2);

    // ---- main loop over 49 kernel offsets ----
    for (int k = 0; k < K2; k++){
        int cur = k & 1;
        if (k + 1 < K2){
            const char* src = (const char*)g_Wsp + (size_t)(k+1)*16384;
            uint32_t dst = sb + OFF_B + (cur^1)*16384;
            #pragma unroll
            for (int j = 0; j < 4; j++){
                int idx = tid + j*256;
                cpa16(dst + idx*16, src + idx*16);
            }
            CP_COMMIT();
            CP_WAIT(1);
        } else {
            CP_WAIT(0);
        }
        __syncthreads();

        uint32_t bBase = sb + OFF_B + cur*16384;
        int ki = k / KS, kj = k - ki*KS;
        uint32_t aAddr0 = aStat + (uint32_t)((ki*XC + kj)*HROW);

        float d[16];
        #pragma unroll
        for (int i = 0; i < 16; i++) d[i] = 0.f;

        #pragma unroll
        for (int kc = 0; kc < 4; kc++){
            uint32_t aH[4], aL[4];
            uint32_t aAddr = aAddr0 + kc*32;
            ldsm4(aH, aAddr);
            ldsm4(aL, aAddr + 128);

            uint32_t csw = (uint32_t)(kc*32) + bhalf16;
            uint32_t addr0 = bBase + bOff0 + (csw ^ bXor0);
            uint32_t addr1 = bBase + bOff1 + (csw ^ bXor1);
            uint32_t bh0[4], bh1[4], bl0[4], bl1[4];
            ldsm4(bh0, addr0);
            ldsm4(bh1, addr1);
            ldsm4(bl0, addr0 + 8192);
            ldsm4(bl1, addr1 + 8192);

            // pass-major ordering: 4 independent accumulator groups per pass
            // pass hi*hi
            mma16816(&d[0],  aH, bh0);
            mma16816(&d[4],  aH, bh0+2);
            mma16816(&d[8],  aH, bh1);
            mma16816(&d[12], aH, bh1+2);
            // pass lo*hi
            mma16816(&d[0],  aL, bh0);
            mma16816(&d[4],  aL, bh0+2);
            mma16816(&d[8],  aL, bh1);
            mma16816(&d[12], aL, bh1+2);
            // pass hi*lo
            mma16816(&d[0],  aH, bl0);
            mma16816(&d[4],  aH, bl0+2);
            mma16816(&d[8],  aH, bl1);
            mma16816(&d[12], aH, bl1+2);
        }

        // weight by rw and accumulate
        float r_lo = rw[p_lo*K2 + k];
        float r_hi = rw[(p_lo + 8)*K2 + k];
        #pragma unroll
        for (int g = 0; g < 4; g++){
            acc[g*4 + 0] += r_lo*d[g*4 + 0];
            acc[g*4 + 1] += r_lo*d[g*4 + 1];
            acc[g*4 + 2] += r_hi*d[g*4 + 2];
            acc[g*4 + 3] += r_hi*d[g*4 + 3];
        }
        __syncthreads();   // all warps done reading B buf before it is overwritten
    }

    // ---- store ----
    {
        int p_hi  = p_lo + 8;
        int gh_lo = gh0 + (p_lo >> 3), gw_lo = gw0 + (p_lo & 7);
        int gh_hi = gh0 + (p_hi >> 3), gw_hi = gw0 + (p_hi & 7);
        #pragma unroll
        for (int g = 0; g < 4; g++){
            int o = ni*32 + g*8 + 2*(l & 3);
            float b0 = b_lin[o], b1 = b_lin[o+1];
            out[((size_t)(t*C_ + o  )*H_ + gh_lo)*W_ + gw_lo] = acc[g*4 + 0] + b0;
            out[((size_t)(t*C_ + o+1)*H_ + gh_lo)*W_ + gw_lo] = acc[g*4 + 1] + b1;
            out[((size_t)(t*C_ + o  )*H_ + gh_hi)*W_ + gw_hi] = acc[g*4 + 2] + b0;
            out[((size_t)(t*C_ + o+1)*H_ + gh_hi)*W_ + gw_hi] = acc[g*4 + 3] + b1;
        }
    }
}

// ========================= launch =========================

extern "C" void kernel_launch(void* const* d_in, const int* in_sizes, int n_in,
                              void* d_out, int out_size)
{
    const float* x       = (const float*)d_in[0];
    const int*   spix    = (const int*)  d_in[1];
    const float* W       = (const float*)d_in[2];
    const float* b_lin   = (const float*)d_in[3];
    const float* w_scale = (const float*)d_in[4];
    const float* b_scale = (const float*)d_in[5];
    float* out = (float*)d_out;

    cudaFuncSetAttribute(pwd_kernel,  cudaFuncAttributeMaxDynamicSharedMemorySize, PWD_SMEM);
    cudaFuncSetAttribute(main_kernel, cudaFuncAttributeMaxDynamicSharedMemorySize, SMEM_MAIN);

    zero_kernel  <<<(T_*NSPIX*C_ + 255)/256, 256>>>();
    wsplit_kernel<<<C_, 256>>>(W);
    accum_kernel <<<(T_*H_*W_ + 7)/8, 256>>>(x, spix);
    pwd_kernel   <<<T_*49, 256, PWD_SMEM>>>();

    dim3 grid(W_/TW, H_/TH, T_);
    main_kernel<<<grid, 256, SMEM_MAIN>>>(x, spix, b_lin, w_scale, b_scale, out);
}